// round 4
// baseline (speedup 1.0000x reference)
#include <cuda_runtime.h>

#define IMG 256
#define NEAR_F 0.1f
#define FAR_F 100.0f
#define REPS 1e-8f
#define ORIG 1024.0f

#define BMAX 4
#define VMAX 5000
#define FMAX 10000
#define NFACE (BMAX * FMAX)
#define TPI 32                        // 32x32 tiles of 8x8 px per image
#define TSZ 8
#define NTILEMAX (BMAX * TPI * TPI)   // 4096
#define CULL_M 1e-4f

// ---------------- scratch ----------------
__device__ float  g_vndc[BMAX * VMAX * 3];
__device__ float4 g_rec[NFACE * 5];
__device__ float  g_zminf[NFACE];
__device__ int4   g_trange[NFACE];
__device__ int    g_count[NTILEMAX];
__device__ int    g_fill[NTILEMAX];
__device__ int    g_offset[NTILEMAX];
__device__ int    g_list [NFACE * TPI * TPI / 40];   // cap: avg 25.6 tiles/face...
// NOTE: capacity reasoning below — we need worst case; use full bound instead:
__device__ int    g_listA[NFACE * 1024];
__device__ int    g_listB[NFACE * 1024];

__device__ __forceinline__ int zbucket(float z) {
    int q = (int)floorf((z - 1.0f) * 64.0f);
    return max(0, min(255, q));
}
__device__ __forceinline__ float zbound(int q) {
    return (q <= 0) ? 0.0f : (1.0f + (float)q * 0.015625f - 1e-4f);
}

// ---------------- projection ----------------
__global__ void project_kernel(const float* __restrict__ verts,
                               const float* __restrict__ K,
                               const float* __restrict__ R,
                               const float* __restrict__ t,
                               const float* __restrict__ dist,
                               int B, int V) {
    int idx = blockIdx.x * blockDim.x + threadIdx.x;
    if (idx >= B * V) return;
    int b = idx / V;
    const float* vp = verts + (size_t)idx * 3;
    const float* Rb = R + b * 9;
    const float* tb = t + b * 3;
    const float* Kb = K + b * 9;
    const float* db = dist + b * 5;

    float vx = vp[0], vy = vp[1], vz = vp[2];
    float x = Rb[0] * vx + Rb[1] * vy + Rb[2] * vz + tb[0];
    float y = Rb[3] * vx + Rb[4] * vy + Rb[5] * vz + tb[1];
    float z = Rb[6] * vx + Rb[7] * vy + Rb[8] * vz + tb[2];

    float x_ = x / (z + 1e-9f);
    float y_ = y / (z + 1e-9f);
    float k1 = db[0], k2 = db[1], p1 = db[2], p2 = db[3], k3 = db[4];
    float r2 = x_ * x_ + y_ * y_;
    float rad = 1.0f + k1 * r2 + k2 * r2 * r2 + k3 * r2 * r2 * r2;
    float x__ = x_ * rad + 2.0f * p1 * x_ * y_ + p2 * (r2 + 2.0f * x_ * x_);
    float y__ = y_ * rad + p1 * (r2 + 2.0f * y_ * y_) + 2.0f * p2 * x_ * y_;

    float u  = Kb[0] * x__ + Kb[1] * y__ + Kb[2];
    float vc = Kb[3] * x__ + Kb[4] * y__ + Kb[5];
    vc = ORIG - vc;
    u  = 2.0f * (u  - ORIG * 0.5f) / ORIG;
    vc = 2.0f * (vc - ORIG * 0.5f) / ORIG;

    float* o = g_vndc + (size_t)idx * 3;
    o[0] = u; o[1] = vc; o[2] = z;
}

// ---------------- zero counters ----------------
__global__ void zero_kernel(int ntile) {
    int i = blockIdx.x * blockDim.x + threadIdx.x;
    if (i < ntile) { g_count[i] = 0; g_fill[i] = 0; }
}

// ---------------- per-face prep + tile counting ----------------
__global__ void prep_kernel(const int* __restrict__ faces, int B, int V, int F) {
    int idx = blockIdx.x * blockDim.x + threadIdx.x;
    if (idx >= B * F) return;
    int b = idx / F;
    const int* fp = faces + (size_t)idx * 3;
    int i0 = fp[0], i1 = fp[1], i2 = fp[2];
    const float* base = g_vndc + (size_t)b * V * 3;
    float x0 = base[i0*3+0], y0 = base[i0*3+1], z0 = base[i0*3+2];
    float x1 = base[i1*3+0], y1 = base[i1*3+1], z1 = base[i1*3+2];
    float x2 = base[i2*3+0], y2 = base[i2*3+1], z2 = base[i2*3+2];

    int4 empty; empty.x = 1; empty.y = 1; empty.z = 0; empty.w = 0;

    if (!(z0 > REPS && z1 > REPS && z2 > REPS)) { g_trange[idx] = empty; return; }

    float df = (y1 - y2) * (x0 - x2) + (x2 - x1) * (y0 - y2);
    float dr = (y1 - y0) * (x2 - x0) + (x0 - x1) * (y2 - y0);
    bool okf = fabsf(df) > REPS;
    bool okr = fabsf(dr) > REPS;
    if (!okf && !okr) { g_trange[idx] = empty; return; }

    float xmin = fminf(x0, fminf(x1, x2)), xmax = fmaxf(x0, fmaxf(x1, x2));
    float ymin = fminf(y0, fminf(y1, y2)), ymax = fmaxf(y0, fmaxf(y1, y2));
    const float Sf = (float)IMG;
    int c_lo = max(0,       (int)floorf((xmin * Sf + Sf - 1.0f) * 0.5f));
    int c_hi = min(IMG - 1, (int)ceilf ((xmax * Sf + Sf - 1.0f) * 0.5f));
    int r_lo = max(0,       (int)floorf((ymin * Sf + Sf - 1.0f) * 0.5f));
    int r_hi = min(IMG - 1, (int)ceilf ((ymax * Sf + Sf - 1.0f) * 0.5f));
    if (c_lo > c_hi || r_lo > r_hi) { g_trange[idx] = empty; return; }

    int4 tr; tr.x = c_lo >> 3; tr.y = r_lo >> 3; tr.z = c_hi >> 3; tr.w = r_hi >> 3;
    g_trange[idx] = tr;
    float zmf = fminf(z0, fminf(z1, z2));
    g_zminf[idx] = zmf;

    int tb = b * TPI * TPI;
    for (int ty = tr.y; ty <= tr.w; ty++)
        for (int tx = tr.x; tx <= tr.z; tx++)
            atomicAdd(&g_count[tb + ty * TPI + tx], 1);

    float nanv = __int_as_float(0x7fffffff);
    float invdf = okf ? (1.0f / df) : nanv;
    float invdr = okr ? (1.0f / dr) : nanv;
    float iz0 = 1.0f / z0, iz1 = 1.0f / z1, iz2 = 1.0f / z2;

    float4 r0; r0.x = x2;      r0.y = y2;      r0.z = x0;      r0.w = y0;
    float4 r1; r1.x = y1 - y2; r1.y = x2 - x1; r1.z = y2 - y0; r1.w = x0 - x2;
    float4 r2f; r2f.x = y1 - y0; r2f.y = x0 - x1; r2f.z = y0 - y2; r2f.w = x2 - x0;
    float4 r3; r3.x = invdf;   r3.y = invdr;   r3.z = zmf;       r3.w = iz0 - iz2;  // af
    float4 r4; r4.x = iz1 - iz2; r4.y = iz2;   r4.z = iz1 - iz0; r4.w = iz0;        // bf,cf,br,cr
    g_rec[idx*5+0] = r0; g_rec[idx*5+1] = r1; g_rec[idx*5+2] = r2f;
    g_rec[idx*5+3] = r3; g_rec[idx*5+4] = r4;
}

// ---------------- prefix scan of 4096 tile counts (1 block, 4/thread) ----------------
__global__ void scan_kernel(int ntile) {
    __shared__ int s[1024];
    int t = threadIdx.x;
    int i0 = t * 4;
    int v0 = (i0 + 0 < ntile) ? g_count[i0 + 0] : 0;
    int v1 = (i0 + 1 < ntile) ? g_count[i0 + 1] : 0;
    int v2 = (i0 + 2 < ntile) ? g_count[i0 + 2] : 0;
    int v3 = (i0 + 3 < ntile) ? g_count[i0 + 3] : 0;
    int sum = v0 + v1 + v2 + v3;
    s[t] = sum;
    for (int off = 1; off < 1024; off <<= 1) {
        __syncthreads();
        int add = (t >= off) ? s[t - off] : 0;
        __syncthreads();
        s[t] += add;
    }
    int excl = s[t] - sum;
    if (i0 + 0 < ntile) g_offset[i0 + 0] = excl;
    if (i0 + 1 < ntile) g_offset[i0 + 1] = excl + v0;
    if (i0 + 2 < ntile) g_offset[i0 + 2] = excl + v0 + v1;
    if (i0 + 3 < ntile) g_offset[i0 + 3] = excl + v0 + v1 + v2;
}

// ---------------- fill lists with conservative tile culling ----------------
__global__ void fill_kernel(int B, int F) {
    int idx = blockIdx.x * blockDim.x + threadIdx.x;
    if (idx >= B * F) return;
    int4 tr = g_trange[idx];
    if (tr.x > tr.z) return;
    int b = idx / F;

    float4 r0 = g_rec[idx*5+0];
    float4 r1 = g_rec[idx*5+1];
    float4 r3 = g_rec[idx*5+3];
    float x2 = r0.x, y2 = r0.y;
    float invdf = r3.x;
    const float Sf = (float)IMG;
    int tbase = b * TPI * TPI;

    for (int ty = tr.y; ty <= tr.w; ty++) {
        float ylo = (2.0f * (float)(ty * TSZ)           + 1.0f - Sf) / Sf;
        float yhi = (2.0f * (float)(ty * TSZ + TSZ - 1) + 1.0f - Sf) / Sf;
        for (int tx = tr.x; tx <= tr.z; tx++) {
            float xlo = (2.0f * (float)(tx * TSZ)           + 1.0f - Sf) / Sf;
            float xhi = (2.0f * (float)(tx * TSZ + TSZ - 1) + 1.0f - Sf) / Sf;

            float m0 = -1e30f, m1 = -1e30f, m2 = -1e30f;
            #pragma unroll
            for (int cidx = 0; cidx < 4; cidx++) {
                float cx = (cidx & 1) ? xhi : xlo;
                float cy = (cidx & 2) ? yhi : ylo;
                float dx = cx - x2, dy = cy - y2;
                float w0 = (r1.x * dx + r1.y * dy) * invdf;
                float w1 = (r1.z * dx + r1.w * dy) * invdf;
                float w2 = 1.0f - w0 - w1;
                m0 = fmaxf(m0, w0); m1 = fmaxf(m1, w1); m2 = fmaxf(m2, w2);
            }
            if (m0 < -CULL_M || m1 < -CULL_M || m2 < -CULL_M) continue;

            int t = tbase + ty * TPI + tx;
            int pos = g_offset[t] + atomicAdd(&g_fill[t], 1);
            g_listA[pos] = idx;
        }
    }
}

// ---------------- per-tile counting sort by z-bucket ----------------
__global__ void sort_kernel() {
    int tile = blockIdx.x;
    int len  = g_fill[tile];
    if (len == 0) return;
    int base = g_offset[tile];
    int tid = threadIdx.x;

    __shared__ int cnt[256];
    __shared__ int off[256];
    cnt[tid] = 0;
    __syncthreads();

    for (int i = tid; i < len; i += 256) {
        int f = g_listA[base + i];
        atomicAdd(&cnt[zbucket(g_zminf[f])], 1);
    }
    __syncthreads();

    int v = cnt[tid];
    off[tid] = v;
    for (int o = 1; o < 256; o <<= 1) {
        __syncthreads();
        int add = (tid >= o) ? off[tid - o] : 0;
        __syncthreads();
        off[tid] += add;
    }
    __syncthreads();
    int start = off[tid] - v;
    __syncthreads();
    off[tid] = start;
    __syncthreads();

    for (int i = tid; i < len; i += 256) {
        int f = g_listA[base + i];
        int q = zbucket(g_zminf[f]);
        int pos = atomicAdd(&off[q], 1);
        g_listB[base + pos] = f;
    }
}

// ---------------- raster: 8x8 tile, 2 independent warps, direct store ----------------
__global__ void __launch_bounds__(64) raster_tiles(float* __restrict__ out) {
    int tile = blockIdx.x;             // b*1024 + ty*32 + tx
    int b  = tile >> 10;
    int tt = tile & 1023;
    int ty = tt >> 5, tx = tt & 31;
    int tid = threadIdx.x;
    int r = ty * TSZ + (tid >> 3);
    int c = tx * TSZ + (tid & 7);
    const float Sf = (float)IMG;
    float xp = (2.0f * (float)c + 1.0f - Sf) / Sf;
    float yp = (2.0f * (float)r + 1.0f - Sf) / Sf;

    int len   = g_fill[tile];
    int basei = g_offset[tile];
    float zmin = FAR_F;
    const unsigned FULL = 0xffffffffu;

    if (len > 0) {
        int f0 = __ldg(&g_listB[basei]);
        float4 p0 = __ldg(&g_rec[f0*5+0]);
        float4 p1 = __ldg(&g_rec[f0*5+1]);
        float4 p2 = __ldg(&g_rec[f0*5+2]);
        float4 p3 = __ldg(&g_rec[f0*5+3]);
        float4 p4 = __ldg(&g_rec[f0*5+4]);

        for (int i = 0; i < len; i++) {
            float4 q0 = p0, q1 = p1, q2 = p2, q3 = p3, q4 = p4;
            int nx = min(i + 1, len - 1);
            int fn = __ldg(&g_listB[basei + nx]);
            p0 = __ldg(&g_rec[fn*5+0]);
            p1 = __ldg(&g_rec[fn*5+1]);
            p2 = __ldg(&g_rec[fn*5+2]);
            p3 = __ldg(&g_rec[fn*5+3]);
            p4 = __ldg(&g_rec[fn*5+4]);

            float zf = q3.z;
            float bound = zbound(zbucket(zf));
            // all remaining faces have zminf >= bound; if every lane is already
            // at or below it, this warp is done.
            if (!__ballot_sync(FULL, zmin > bound)) break;

            if (__ballot_sync(FULL, zf < zmin)) {
                float dxf = xp - q0.x, dyf = yp - q0.y;
                float u0 = q1.x * dxf + q1.y * dyf;
                float u1 = q1.z * dxf + q1.w * dyf;
                float w0 = u0 * q3.x, w1 = u1 * q3.x;
                float w2 = 1.0f - w0 - w1;
                bool inf_ = (w0 >= 0.0f) && (w1 >= 0.0f) && (w2 >= 0.0f);

                float dxr = xp - q0.z, dyr = yp - q0.w;
                float v0 = q2.x * dxr + q2.y * dyr;
                float v1 = q2.z * dxr + q2.w * dyr;
                float w0r = v0 * q3.y, w1r = v1 * q3.y;
                float w2r = 1.0f - w0r - w1r;
                bool inr_ = (w0r >= 0.0f) && (w1r >= 0.0f) && (w2r >= 0.0f);

                if (inf_ || inr_) {
                    float zinv = inf_ ? fmaf(w1,  q4.x, fmaf(w0,   q3.w, q4.y))
                                      : fmaf(w1r, q4.z, fmaf(w0r, -q3.w, q4.w));
                    float zp = (zinv > REPS) ? __fdividef(1.0f, zinv) : 1.0f;
                    if (zp > NEAR_F && zp < FAR_F) zmin = fminf(zmin, zp);
                }
            }
        }
    }

    // tiles partition the image: exactly one lane owns each pixel -> plain store
    out[((size_t)b * IMG + (IMG - 1 - r)) * IMG + c] = zmin;
}

extern "C" void kernel_launch(void* const* d_in, const int* in_sizes, int n_in,
                              void* d_out, int out_size) {
    const float* verts = (const float*)d_in[0];
    const int*   faces = (const int*)d_in[1];
    const float* K     = (const float*)d_in[2];
    const float* R     = (const float*)d_in[3];
    const float* t     = (const float*)d_in[4];
    const float* dist  = (const float*)d_in[5];
    float* out = (float*)d_out;

    int B = in_sizes[2] / 9;
    int V = in_sizes[0] / (3 * B);
    int F = in_sizes[1] / (3 * B);
    int ntile = B * TPI * TPI;

    int nv = B * V;
    project_kernel<<<(nv + 255) / 256, 256>>>(verts, K, R, t, dist, B, V);

    zero_kernel<<<(ntile + 255) / 256, 256>>>(ntile);

    int nf = B * F;
    prep_kernel<<<(nf + 255) / 256, 256>>>(faces, B, V, F);

    scan_kernel<<<1, 1024>>>(ntile);

    fill_kernel<<<(nf + 255) / 256, 256>>>(B, F);

    sort_kernel<<<ntile, 256>>>();

    raster_tiles<<<ntile, 64>>>(out);
}

// round 5
// speedup vs baseline: 1.9508x; 1.9508x over previous
#include <cuda_runtime.h>

#define IMG 256
#define NEAR_F 0.1f
#define FAR_F 100.0f
#define REPS 1e-8f
#define ORIG 1024.0f

#define BMAX 4
#define VMAX 5000
#define FMAX 10000
#define NFACE (BMAX * FMAX)
#define TPI 16                        // 16x16 tiles of 16x16 px per image
#define TSZ 16
#define NTILEMAX (BMAX * TPI * TPI)   // 1024
#define CH 32
#define K0 256                        // phase-1 depth of sorted list
#define SPLIT 8
#define CULL_M 1e-4f

// ---------------- scratch ----------------
__device__ float  g_vndc[BMAX * VMAX * 3];
__device__ float4 g_rec[NFACE * 5];
__device__ float  g_zminf[NFACE];
__device__ int4   g_trange[NFACE];
__device__ int    g_count[NTILEMAX];
__device__ int    g_fill[NTILEMAX];
__device__ int    g_offset[NTILEMAX];
__device__ int    g_listA[NFACE * 256];   // face can hit at most 256 tiles of its image
__device__ int    g_listB[NFACE * 256];

__device__ __forceinline__ int zbucket(float z) {
    int q = (int)floorf((z - 0.5f) * 64.0f);
    return max(0, min(255, q));
}
__device__ __forceinline__ float zbound(int q) {
    return (q <= 0) ? 0.0f : (0.5f + (float)q * 0.015625f - 1e-4f);
}

// ---------------- projection ----------------
__global__ void project_kernel(const float* __restrict__ verts,
                               const float* __restrict__ K,
                               const float* __restrict__ R,
                               const float* __restrict__ t,
                               const float* __restrict__ dist,
                               int B, int V) {
    int idx = blockIdx.x * blockDim.x + threadIdx.x;
    if (idx >= B * V) return;
    int b = idx / V;
    const float* vp = verts + (size_t)idx * 3;
    const float* Rb = R + b * 9;
    const float* tb = t + b * 3;
    const float* Kb = K + b * 9;
    const float* db = dist + b * 5;

    float vx = vp[0], vy = vp[1], vz = vp[2];
    float x = Rb[0] * vx + Rb[1] * vy + Rb[2] * vz + tb[0];
    float y = Rb[3] * vx + Rb[4] * vy + Rb[5] * vz + tb[1];
    float z = Rb[6] * vx + Rb[7] * vy + Rb[8] * vz + tb[2];

    float x_ = x / (z + 1e-9f);
    float y_ = y / (z + 1e-9f);
    float k1 = db[0], k2 = db[1], p1 = db[2], p2 = db[3], k3 = db[4];
    float r2 = x_ * x_ + y_ * y_;
    float rad = 1.0f + k1 * r2 + k2 * r2 * r2 + k3 * r2 * r2 * r2;
    float x__ = x_ * rad + 2.0f * p1 * x_ * y_ + p2 * (r2 + 2.0f * x_ * x_);
    float y__ = y_ * rad + p1 * (r2 + 2.0f * y_ * y_) + 2.0f * p2 * x_ * y_;

    float u  = Kb[0] * x__ + Kb[1] * y__ + Kb[2];
    float vc = Kb[3] * x__ + Kb[4] * y__ + Kb[5];
    vc = ORIG - vc;
    u  = 2.0f * (u  - ORIG * 0.5f) / ORIG;
    vc = 2.0f * (vc - ORIG * 0.5f) / ORIG;

    float* o = g_vndc + (size_t)idx * 3;
    o[0] = u; o[1] = vc; o[2] = z;
}

// ---------------- zero counters ----------------
__global__ void zero_kernel(int ntile) {
    int i = blockIdx.x * blockDim.x + threadIdx.x;
    if (i < ntile) { g_count[i] = 0; g_fill[i] = 0; }
}

// ---------------- per-face prep + tile counting ----------------
__global__ void prep_kernel(const int* __restrict__ faces, int B, int V, int F) {
    int idx = blockIdx.x * blockDim.x + threadIdx.x;
    if (idx >= B * F) return;
    int b = idx / F;
    const int* fp = faces + (size_t)idx * 3;
    int i0 = fp[0], i1 = fp[1], i2 = fp[2];
    const float* base = g_vndc + (size_t)b * V * 3;
    float x0 = base[i0*3+0], y0 = base[i0*3+1], z0 = base[i0*3+2];
    float x1 = base[i1*3+0], y1 = base[i1*3+1], z1 = base[i1*3+2];
    float x2 = base[i2*3+0], y2 = base[i2*3+1], z2 = base[i2*3+2];

    int4 empty; empty.x = 1; empty.y = 1; empty.z = 0; empty.w = 0;

    if (!(z0 > REPS && z1 > REPS && z2 > REPS)) { g_trange[idx] = empty; return; }

    float df = (y1 - y2) * (x0 - x2) + (x2 - x1) * (y0 - y2);
    float dr = (y1 - y0) * (x2 - x0) + (x0 - x1) * (y2 - y0);
    bool okf = fabsf(df) > REPS;
    bool okr = fabsf(dr) > REPS;
    if (!okf && !okr) { g_trange[idx] = empty; return; }

    float xmin = fminf(x0, fminf(x1, x2)), xmax = fmaxf(x0, fmaxf(x1, x2));
    float ymin = fminf(y0, fminf(y1, y2)), ymax = fmaxf(y0, fmaxf(y1, y2));
    const float Sf = (float)IMG;
    int c_lo = max(0,       (int)floorf((xmin * Sf + Sf - 1.0f) * 0.5f));
    int c_hi = min(IMG - 1, (int)ceilf ((xmax * Sf + Sf - 1.0f) * 0.5f));
    int r_lo = max(0,       (int)floorf((ymin * Sf + Sf - 1.0f) * 0.5f));
    int r_hi = min(IMG - 1, (int)ceilf ((ymax * Sf + Sf - 1.0f) * 0.5f));
    if (c_lo > c_hi || r_lo > r_hi) { g_trange[idx] = empty; return; }

    int4 tr; tr.x = c_lo >> 4; tr.y = r_lo >> 4; tr.z = c_hi >> 4; tr.w = r_hi >> 4;
    g_trange[idx] = tr;
    float zmf = fminf(z0, fminf(z1, z2));
    g_zminf[idx] = zmf;

    int tb = b * TPI * TPI;
    for (int ty = tr.y; ty <= tr.w; ty++)
        for (int tx = tr.x; tx <= tr.z; tx++)
            atomicAdd(&g_count[tb + ty * TPI + tx], 1);

    float nanv = __int_as_float(0x7fffffff);
    float invdf = okf ? (1.0f / df) : nanv;
    float invdr = okr ? (1.0f / dr) : nanv;
    float iz0 = 1.0f / z0, iz1 = 1.0f / z1, iz2 = 1.0f / z2;

    float4 r0; r0.x = x2;      r0.y = y2;      r0.z = x0;      r0.w = y0;
    float4 r1; r1.x = y1 - y2; r1.y = x2 - x1; r1.z = y2 - y0; r1.w = x0 - x2;
    float4 r2f; r2f.x = y1 - y0; r2f.y = x0 - x1; r2f.z = y0 - y2; r2f.w = x2 - x0;
    float4 r3; r3.x = invdf;   r3.y = invdr;   r3.z = zmf;       r3.w = iz0 - iz2;  // af
    float4 r4; r4.x = iz1 - iz2; r4.y = iz2;   r4.z = iz1 - iz0; r4.w = iz0;        // bf,cf,br,cr
    g_rec[idx*5+0] = r0; g_rec[idx*5+1] = r1; g_rec[idx*5+2] = r2f;
    g_rec[idx*5+3] = r3; g_rec[idx*5+4] = r4;
}

// ---------------- prefix scan of tile counts ----------------
__global__ void scan_kernel(int ntile) {
    __shared__ int s[NTILEMAX];
    int t = threadIdx.x;
    int v = (t < ntile) ? g_count[t] : 0;
    s[t] = v;
    for (int off = 1; off < NTILEMAX; off <<= 1) {
        __syncthreads();
        int add = (t >= off) ? s[t - off] : 0;
        __syncthreads();
        s[t] += add;
    }
    if (t < ntile) g_offset[t] = s[t] - v;
}

// ---------------- fill lists with conservative tile culling ----------------
__global__ void fill_kernel(int B, int F) {
    int idx = blockIdx.x * blockDim.x + threadIdx.x;
    if (idx >= B * F) return;
    int4 tr = g_trange[idx];
    if (tr.x > tr.z) return;
    int b = idx / F;

    float4 r0 = g_rec[idx*5+0];
    float4 r1 = g_rec[idx*5+1];
    float4 r3 = g_rec[idx*5+3];
    float x2 = r0.x, y2 = r0.y;
    float invdf = r3.x;
    const float Sf = (float)IMG;
    int tbase = b * TPI * TPI;

    for (int ty = tr.y; ty <= tr.w; ty++) {
        float ylo = (2.0f * (float)(ty * TSZ)           + 1.0f - Sf) / Sf;
        float yhi = (2.0f * (float)(ty * TSZ + TSZ - 1) + 1.0f - Sf) / Sf;
        for (int tx = tr.x; tx <= tr.z; tx++) {
            float xlo = (2.0f * (float)(tx * TSZ)           + 1.0f - Sf) / Sf;
            float xhi = (2.0f * (float)(tx * TSZ + TSZ - 1) + 1.0f - Sf) / Sf;

            float m0 = -1e30f, m1 = -1e30f, m2 = -1e30f;
            #pragma unroll
            for (int cidx = 0; cidx < 4; cidx++) {
                float cx = (cidx & 1) ? xhi : xlo;
                float cy = (cidx & 2) ? yhi : ylo;
                float dx = cx - x2, dy = cy - y2;
                float w0 = (r1.x * dx + r1.y * dy) * invdf;
                float w1 = (r1.z * dx + r1.w * dy) * invdf;
                float w2 = 1.0f - w0 - w1;
                m0 = fmaxf(m0, w0); m1 = fmaxf(m1, w1); m2 = fmaxf(m2, w2);
            }
            if (m0 < -CULL_M || m1 < -CULL_M || m2 < -CULL_M) continue;

            int t = tbase + ty * TPI + tx;
            int pos = g_offset[t] + atomicAdd(&g_fill[t], 1);
            g_listA[pos] = idx;
        }
    }
}

// ---------------- per-tile counting sort by z-bucket ----------------
__global__ void sort_kernel() {
    int tile = blockIdx.x;
    int len  = g_fill[tile];
    if (len == 0) return;
    int base = g_offset[tile];
    int tid = threadIdx.x;

    __shared__ int cnt[256];
    __shared__ int off[256];
    cnt[tid] = 0;
    __syncthreads();

    for (int i = tid; i < len; i += 256) {
        int f = g_listA[base + i];
        atomicAdd(&cnt[zbucket(g_zminf[f])], 1);
    }
    __syncthreads();

    int v = cnt[tid];
    off[tid] = v;
    for (int o = 1; o < 256; o <<= 1) {
        __syncthreads();
        int add = (tid >= o) ? off[tid - o] : 0;
        __syncthreads();
        off[tid] += add;
    }
    __syncthreads();
    int start = off[tid] - v;
    __syncthreads();
    off[tid] = start;
    __syncthreads();

    for (int i = tid; i < len; i += 256) {
        int f = g_listA[base + i];
        int q = zbucket(g_zminf[f]);
        int pos = atomicAdd(&off[q], 1);
        g_listB[base + pos] = f;
    }
}

// ---------------- shared raster body over [j0, j1) of a tile list ----------------
__device__ __forceinline__ float raster_range(int basei, int j0, int j1,
                                              float xp, float yp, float zmin,
                                              float4* srec, int tid) {
    const unsigned FULL = 0xffffffffu;
    for (int j = j0; j < j1; j += CH) {
        int n = min(CH, j1 - j);
        __syncthreads();
        for (int k = tid; k < n * 5; k += 256) {
            int m = k / 5;
            int q = k - m * 5;
            int fidx = g_listB[basei + j + m];
            srec[k] = g_rec[fidx * 5 + q];
        }
        __syncthreads();

        float bound = zbound(zbucket(srec[3].z));        // first face of chunk
        if (__syncthreads_and(zmin <= bound)) break;     // whole block done
        if (!__ballot_sync(FULL, zmin > bound)) continue; // this warp done (for now)

        for (int m = 0; m < n; m++) {
            float4 q3 = srec[m*5+3];
            if (!__ballot_sync(FULL, q3.z < zmin)) continue;  // face can't help warp

            float4 q0 = srec[m*5+0];
            float4 q1 = srec[m*5+1];
            float4 q2 = srec[m*5+2];
            float4 q4 = srec[m*5+4];

            float dxf = xp - q0.x, dyf = yp - q0.y;
            float u0 = q1.x * dxf + q1.y * dyf;
            float u1 = q1.z * dxf + q1.w * dyf;
            float w0 = u0 * q3.x, w1 = u1 * q3.x;
            float w2 = 1.0f - w0 - w1;
            bool inf_ = (w0 >= 0.0f) && (w1 >= 0.0f) && (w2 >= 0.0f);

            float dxr = xp - q0.z, dyr = yp - q0.w;
            float v0 = q2.x * dxr + q2.y * dyr;
            float v1 = q2.z * dxr + q2.w * dyr;
            float w0r = v0 * q3.y, w1r = v1 * q3.y;
            float w2r = 1.0f - w0r - w1r;
            bool inr_ = (w0r >= 0.0f) && (w1r >= 0.0f) && (w2r >= 0.0f);

            if (inf_ || inr_) {
                float zinv = inf_ ? fmaf(w1,  q4.x, fmaf(w0,   q3.w, q4.y))
                                  : fmaf(w1r, q4.z, fmaf(w0r, -q3.w, q4.w));
                float zp = (zinv > REPS) ? __fdividef(1.0f, zinv) : 1.0f;
                if (zp > NEAR_F && zp < FAR_F) zmin = fminf(zmin, zp);
            }
        }
    }
    return zmin;
}

// ---------------- phase 1: first K0 sorted faces, plain store ----------------
__global__ void __launch_bounds__(256) raster_p1(float* __restrict__ out) {
    int tile = blockIdx.x;
    int b  = tile >> 8;
    int tt = tile & 255;
    int ty = tt >> 4, tx = tt & 15;
    int tid = threadIdx.x;
    int r = ty * TSZ + (tid >> 4);
    int c = tx * TSZ + (tid & 15);
    const float Sf = (float)IMG;
    float xp = (2.0f * (float)c + 1.0f - Sf) / Sf;
    float yp = (2.0f * (float)r + 1.0f - Sf) / Sf;

    int len   = min(g_fill[tile], K0);
    int basei = g_offset[tile];

    __shared__ float4 srec[CH * 5];
    float zmin = raster_range(basei, 0, len, xp, yp, FAR_F, srec, tid);

    out[((size_t)b * IMG + (IMG - 1 - r)) * IMG + c] = zmin;
}

// ---------------- phase 2: tail split across SPLIT blocks, seeded from out ----------------
__global__ void __launch_bounds__(256) raster_p2(float* __restrict__ out) {
    int tile  = blockIdx.x / SPLIT;
    int slice = blockIdx.x % SPLIT;
    int len = g_fill[tile];
    if (len <= K0) return;
    int rem = len - K0;

    int b  = tile >> 8;
    int tt = tile & 255;
    int ty = tt >> 4, tx = tt & 15;
    int tid = threadIdx.x;
    int r = ty * TSZ + (tid >> 4);
    int c = tx * TSZ + (tid & 15);
    const float Sf = (float)IMG;
    float xp = (2.0f * (float)c + 1.0f - Sf) / Sf;
    float yp = (2.0f * (float)r + 1.0f - Sf) / Sf;

    int basei = g_offset[tile];
    int j0 = K0 + (int)(((long long)rem * slice) / SPLIT);
    int j1 = K0 + (int)(((long long)rem * (slice + 1)) / SPLIT);
    if (j0 >= j1) return;

    size_t pix = ((size_t)b * IMG + (IMG - 1 - r)) * IMG + c;
    float cur = out[pix];                       // phase-1 result (kernel order guarantees)

    __shared__ float4 srec[CH * 5];
    float zmin = raster_range(basei, j0, j1, xp, yp, cur, srec, tid);

    if (zmin < cur)
        atomicMin((int*)&out[pix], __float_as_int(zmin));
}

extern "C" void kernel_launch(void* const* d_in, const int* in_sizes, int n_in,
                              void* d_out, int out_size) {
    const float* verts = (const float*)d_in[0];
    const int*   faces = (const int*)d_in[1];
    const float* K     = (const float*)d_in[2];
    const float* R     = (const float*)d_in[3];
    const float* t     = (const float*)d_in[4];
    const float* dist  = (const float*)d_in[5];
    float* out = (float*)d_out;

    int B = in_sizes[2] / 9;
    int V = in_sizes[0] / (3 * B);
    int F = in_sizes[1] / (3 * B);
    int ntile = B * TPI * TPI;

    int nv = B * V;
    project_kernel<<<(nv + 255) / 256, 256>>>(verts, K, R, t, dist, B, V);

    zero_kernel<<<(ntile + 255) / 256, 256>>>(ntile);

    int nf = B * F;
    prep_kernel<<<(nf + 255) / 256, 256>>>(faces, B, V, F);

    scan_kernel<<<1, NTILEMAX>>>(ntile);

    fill_kernel<<<(nf + 255) / 256, 256>>>(B, F);

    sort_kernel<<<ntile, 256>>>();

    raster_p1<<<ntile, 256>>>(out);
    raster_p2<<<ntile * SPLIT, 256>>>(out);
}

// round 6
// speedup vs baseline: 2.8041x; 1.4374x over previous
#include <cuda_runtime.h>

#define IMG 256
#define NEAR_F 0.1f
#define FAR_F 100.0f
#define REPS 1e-8f
#define ORIG 1024.0f

#define BMAX 4
#define VMAX 5000
#define FMAX 10000
#define NFACE (BMAX * FMAX)
#define TPI 16                        // 16x16 tiles of 16x16 px per image
#define TSZ 16
#define NTILEMAX (BMAX * TPI * TPI)   // 1024
#define CAP 8192                      // per-tile list capacity
#define CH 32
#define SPLITR 4
#define CULL_M 1e-4f

// ---------------- scratch ----------------
__device__ float  g_vndc[BMAX * VMAX * 3];
__device__ float4 g_rec[NFACE * 5];
__device__ float  g_zminf[NFACE];
__device__ int4   g_trange[NFACE];
__device__ int    g_fill[NTILEMAX];
__device__ int    g_listA[NTILEMAX * CAP];
__device__ int    g_listB[NTILEMAX * CAP];

__device__ __forceinline__ int zbucket(float z) {
    int q = (int)floorf((z - 0.5f) * 64.0f);
    return max(0, min(255, q));
}
__device__ __forceinline__ float zbound(int q) {
    return (q <= 0) ? 0.0f : (0.5f + (float)q * 0.015625f - 1e-4f);
}

// ---------------- projection ----------------
__global__ void project_kernel(const float* __restrict__ verts,
                               const float* __restrict__ K,
                               const float* __restrict__ R,
                               const float* __restrict__ t,
                               const float* __restrict__ dist,
                               int B, int V) {
    int idx = blockIdx.x * blockDim.x + threadIdx.x;
    if (idx >= B * V) return;
    int b = idx / V;
    const float* vp = verts + (size_t)idx * 3;
    const float* Rb = R + b * 9;
    const float* tb = t + b * 3;
    const float* Kb = K + b * 9;
    const float* db = dist + b * 5;

    float vx = vp[0], vy = vp[1], vz = vp[2];
    float x = Rb[0] * vx + Rb[1] * vy + Rb[2] * vz + tb[0];
    float y = Rb[3] * vx + Rb[4] * vy + Rb[5] * vz + tb[1];
    float z = Rb[6] * vx + Rb[7] * vy + Rb[8] * vz + tb[2];

    float x_ = x / (z + 1e-9f);
    float y_ = y / (z + 1e-9f);
    float k1 = db[0], k2 = db[1], p1 = db[2], p2 = db[3], k3 = db[4];
    float r2 = x_ * x_ + y_ * y_;
    float rad = 1.0f + k1 * r2 + k2 * r2 * r2 + k3 * r2 * r2 * r2;
    float x__ = x_ * rad + 2.0f * p1 * x_ * y_ + p2 * (r2 + 2.0f * x_ * x_);
    float y__ = y_ * rad + p1 * (r2 + 2.0f * y_ * y_) + 2.0f * p2 * x_ * y_;

    float u  = Kb[0] * x__ + Kb[1] * y__ + Kb[2];
    float vc = Kb[3] * x__ + Kb[4] * y__ + Kb[5];
    vc = ORIG - vc;
    u  = 2.0f * (u  - ORIG * 0.5f) / ORIG;
    vc = 2.0f * (vc - ORIG * 0.5f) / ORIG;

    float* o = g_vndc + (size_t)idx * 3;
    o[0] = u; o[1] = vc; o[2] = z;
}

// ---------------- per-face prep (no counting) ----------------
__global__ void prep_kernel(const int* __restrict__ faces, int B, int V, int F) {
    int idx = blockIdx.x * blockDim.x + threadIdx.x;
    if (idx >= B * F) return;
    int b = idx / F;
    const int* fp = faces + (size_t)idx * 3;
    int i0 = fp[0], i1 = fp[1], i2 = fp[2];
    const float* base = g_vndc + (size_t)b * V * 3;
    float x0 = base[i0*3+0], y0 = base[i0*3+1], z0 = base[i0*3+2];
    float x1 = base[i1*3+0], y1 = base[i1*3+1], z1 = base[i1*3+2];
    float x2 = base[i2*3+0], y2 = base[i2*3+1], z2 = base[i2*3+2];

    int4 empty; empty.x = 1; empty.y = 1; empty.z = 0; empty.w = 0;

    if (!(z0 > REPS && z1 > REPS && z2 > REPS)) { g_trange[idx] = empty; return; }

    float df = (y1 - y2) * (x0 - x2) + (x2 - x1) * (y0 - y2);
    float dr = (y1 - y0) * (x2 - x0) + (x0 - x1) * (y2 - y0);
    bool okf = fabsf(df) > REPS;
    bool okr = fabsf(dr) > REPS;
    if (!okf && !okr) { g_trange[idx] = empty; return; }

    float xmin = fminf(x0, fminf(x1, x2)), xmax = fmaxf(x0, fmaxf(x1, x2));
    float ymin = fminf(y0, fminf(y1, y2)), ymax = fmaxf(y0, fmaxf(y1, y2));
    const float Sf = (float)IMG;
    int c_lo = max(0,       (int)floorf((xmin * Sf + Sf - 1.0f) * 0.5f));
    int c_hi = min(IMG - 1, (int)ceilf ((xmax * Sf + Sf - 1.0f) * 0.5f));
    int r_lo = max(0,       (int)floorf((ymin * Sf + Sf - 1.0f) * 0.5f));
    int r_hi = min(IMG - 1, (int)ceilf ((ymax * Sf + Sf - 1.0f) * 0.5f));
    if (c_lo > c_hi || r_lo > r_hi) { g_trange[idx] = empty; return; }

    int4 tr; tr.x = c_lo >> 4; tr.y = r_lo >> 4; tr.z = c_hi >> 4; tr.w = r_hi >> 4;
    g_trange[idx] = tr;
    float zmf = fminf(z0, fminf(z1, z2));
    g_zminf[idx] = zmf;

    float nanv = __int_as_float(0x7fffffff);
    float invdf = okf ? (1.0f / df) : nanv;
    float invdr = okr ? (1.0f / dr) : nanv;
    float iz0 = 1.0f / z0, iz1 = 1.0f / z1, iz2 = 1.0f / z2;

    float4 r0; r0.x = x2;      r0.y = y2;      r0.z = x0;      r0.w = y0;
    float4 r1; r1.x = y1 - y2; r1.y = x2 - x1; r1.z = y2 - y0; r1.w = x0 - x2;
    float4 r2f; r2f.x = y1 - y0; r2f.y = x0 - x1; r2f.z = y0 - y2; r2f.w = x2 - x0;
    float4 r3; r3.x = invdf;   r3.y = invdr;   r3.z = zmf;       r3.w = iz0 - iz2;  // af
    float4 r4; r4.x = iz1 - iz2; r4.y = iz2;   r4.z = iz1 - iz0; r4.w = iz0;        // bf,cf,br,cr
    g_rec[idx*5+0] = r0; g_rec[idx*5+1] = r1; g_rec[idx*5+2] = r2f;
    g_rec[idx*5+3] = r3; g_rec[idx*5+4] = r4;
}

// ---------------- fill lists: cheap corner-max edge cull, direct-indexed ----------------
__global__ void fill_kernel(int B, int F) {
    int idx = blockIdx.x * blockDim.x + threadIdx.x;
    if (idx >= B * F) return;
    int4 tr = g_trange[idx];
    if (tr.x > tr.z) return;
    int b = idx / F;

    float4 r0 = g_rec[idx*5+0];
    float4 r1 = g_rec[idx*5+1];
    float4 r3 = g_rec[idx*5+3];
    float x2 = r0.x, y2 = r0.y;
    float invdf = r3.x;
    // w0 = a0*(px-x2) + b0*(py-y2); w1 = a1*..; w2 = 1 - w0 - w1 -> coeffs (-a0-a1, -b0-b1)
    float a0 = r1.x * invdf, b0 = r1.y * invdf;
    float a1 = r1.z * invdf, b1 = r1.w * invdf;
    float a2 = -a0 - a1,     b2 = -b0 - b1;
    const float Sf = (float)IMG;
    int tbase = b * TPI * TPI;

    for (int ty = tr.y; ty <= tr.w; ty++) {
        float ylo = (2.0f * (float)(ty * TSZ)           + 1.0f - Sf) / Sf - y2;
        float yhi = (2.0f * (float)(ty * TSZ + TSZ - 1) + 1.0f - Sf) / Sf - y2;
        for (int tx = tr.x; tx <= tr.z; tx++) {
            float xlo = (2.0f * (float)(tx * TSZ)           + 1.0f - Sf) / Sf - x2;
            float xhi = (2.0f * (float)(tx * TSZ + TSZ - 1) + 1.0f - Sf) / Sf - x2;

            // max of each w over the tile = value at sign-selected corner
            float m0 = a0 * (a0 >= 0.f ? xhi : xlo) + b0 * (b0 >= 0.f ? yhi : ylo);
            float m1 = a1 * (a1 >= 0.f ? xhi : xlo) + b1 * (b1 >= 0.f ? yhi : ylo);
            float m2 = 1.0f + a2 * (a2 >= 0.f ? xhi : xlo) + b2 * (b2 >= 0.f ? yhi : ylo);
            // cull only if definitely fully outside an edge (NaN -> keep)
            if (m0 < -CULL_M || m1 < -CULL_M || m2 < -CULL_M) continue;

            int t = tbase + ty * TPI + tx;
            int pos = atomicAdd(&g_fill[t], 1);
            if (pos < CAP) g_listA[t * CAP + pos] = idx;
        }
    }
}

// ---------------- per-tile counting sort by z-bucket ----------------
__global__ void sort_kernel() {
    int tile = blockIdx.x;
    int len  = min(g_fill[tile], CAP);
    if (len == 0) return;
    int base = tile * CAP;
    int tid = threadIdx.x;

    __shared__ int cnt[256];
    __shared__ int off[256];
    cnt[tid] = 0;
    __syncthreads();

    for (int i = tid; i < len; i += 256) {
        int f = g_listA[base + i];
        atomicAdd(&cnt[zbucket(g_zminf[f])], 1);
    }
    __syncthreads();

    int v = cnt[tid];
    off[tid] = v;
    for (int o = 1; o < 256; o <<= 1) {
        __syncthreads();
        int add = (tid >= o) ? off[tid - o] : 0;
        __syncthreads();
        off[tid] += add;
    }
    __syncthreads();
    int start = off[tid] - v;
    __syncthreads();
    off[tid] = start;
    __syncthreads();

    for (int i = tid; i < len; i += 256) {
        int f = g_listA[base + i];
        int q = zbucket(g_zminf[f]);
        int pos = atomicAdd(&off[q], 1);
        g_listB[base + pos] = f;
    }
}

// ---------------- init output ----------------
__global__ void init_kernel(float* __restrict__ out, int n) {
    int i = blockIdx.x * blockDim.x + threadIdx.x;
    if (i < n) out[i] = FAR_F;
}

// ---------------- raster: interleaved slice split + early-z break ----------------
__global__ void __launch_bounds__(256) raster_tiles(float* __restrict__ out) {
    int tile  = blockIdx.x / SPLITR;
    int slice = blockIdx.x % SPLITR;
    int len = min(g_fill[tile], CAP);
    if (len <= slice * CH) return;

    int b  = tile >> 8;
    int tt = tile & 255;
    int ty = tt >> 4, tx = tt & 15;
    int tid = threadIdx.x;
    int r = ty * TSZ + (tid >> 4);
    int c = tx * TSZ + (tid & 15);
    const float Sf = (float)IMG;
    float xp = (2.0f * (float)c + 1.0f - Sf) / Sf;
    float yp = (2.0f * (float)r + 1.0f - Sf) / Sf;

    int basei = tile * CAP;
    const unsigned FULL = 0xffffffffu;

    __shared__ float4 srec[CH * 5];
    float zmin = FAR_F;

    for (int j = slice * CH; j < len; j += CH * SPLITR) {
        int n = min(CH, len - j);
        __syncthreads();
        for (int k = tid; k < n * 5; k += 256) {
            int m = k / 5;
            int q = k - m * 5;
            int fidx = g_listB[basei + j + m];
            srec[k] = g_rec[fidx * 5 + q];
        }
        __syncthreads();

        // all faces at list index >= j have zminf >= this bucket floor
        float bound = zbound(zbucket(srec[3].z));
        if (__syncthreads_and(zmin <= bound)) break;

        for (int m = 0; m < n; m++) {
            float4 q3 = srec[m*5+3];
            if (!__ballot_sync(FULL, q3.z < zmin)) continue;

            float4 q0 = srec[m*5+0];
            float4 q1 = srec[m*5+1];
            float4 q2 = srec[m*5+2];
            float4 q4 = srec[m*5+4];

            float dxf = xp - q0.x, dyf = yp - q0.y;
            float u0 = q1.x * dxf + q1.y * dyf;
            float u1 = q1.z * dxf + q1.w * dyf;
            float w0 = u0 * q3.x, w1 = u1 * q3.x;
            float w2 = 1.0f - w0 - w1;
            bool inf_ = (w0 >= 0.0f) && (w1 >= 0.0f) && (w2 >= 0.0f);

            float dxr = xp - q0.z, dyr = yp - q0.w;
            float v0 = q2.x * dxr + q2.y * dyr;
            float v1 = q2.z * dxr + q2.w * dyr;
            float w0r = v0 * q3.y, w1r = v1 * q3.y;
            float w2r = 1.0f - w0r - w1r;
            bool inr_ = (w0r >= 0.0f) && (w1r >= 0.0f) && (w2r >= 0.0f);

            if (inf_ || inr_) {
                float zinv = inf_ ? fmaf(w1,  q4.x, fmaf(w0,   q3.w, q4.y))
                                  : fmaf(w1r, q4.z, fmaf(w0r, -q3.w, q4.w));
                float zp = (zinv > REPS) ? __fdividef(1.0f, zinv) : 1.0f;
                if (zp > NEAR_F && zp < FAR_F) zmin = fminf(zmin, zp);
            }
        }
    }

    if (zmin < FAR_F) {
        int* addr = (int*)&out[((size_t)b * IMG + (IMG - 1 - r)) * IMG + c];
        atomicMin(addr, __float_as_int(zmin));
    }
}

extern "C" void kernel_launch(void* const* d_in, const int* in_sizes, int n_in,
                              void* d_out, int out_size) {
    const float* verts = (const float*)d_in[0];
    const int*   faces = (const int*)d_in[1];
    const float* K     = (const float*)d_in[2];
    const float* R     = (const float*)d_in[3];
    const float* t     = (const float*)d_in[4];
    const float* dist  = (const float*)d_in[5];
    float* out = (float*)d_out;

    int B = in_sizes[2] / 9;
    int V = in_sizes[0] / (3 * B);
    int F = in_sizes[1] / (3 * B);
    int ntile = B * TPI * TPI;

    void* fill_ptr = nullptr;
    cudaGetSymbolAddress(&fill_ptr, g_fill);

    int nv = B * V;
    project_kernel<<<(nv + 255) / 256, 256>>>(verts, K, R, t, dist, B, V);

    cudaMemsetAsync(fill_ptr, 0, ntile * sizeof(int));

    int nf = B * F;
    prep_kernel<<<(nf + 255) / 256, 256>>>(faces, B, V, F);

    fill_kernel<<<(nf + 255) / 256, 256>>>(B, F);

    sort_kernel<<<ntile, 256>>>();

    int npix = B * IMG * IMG;
    init_kernel<<<(npix + 255) / 256, 256>>>(out, npix);

    raster_tiles<<<ntile * SPLITR, 256>>>(out);
}

// round 7
// speedup vs baseline: 2.8983x; 1.0336x over previous
#include <cuda_runtime.h>

#define IMG 256
#define NEAR_F 0.1f
#define FAR_F 100.0f
#define REPS 1e-8f
#define ORIG 1024.0f

#define BMAX 4
#define VMAX 5000
#define FMAX 10000
#define NFACE (BMAX * FMAX)
#define TPI 16                        // 16x16 tiles of 16x16 px per image
#define TSZ 16
#define NTILEMAX (BMAX * TPI * TPI)   // 1024
#define CAP 8192
#define CH 32
#define SPLITR 4
#define CULL_M 1e-4f
#define WMARG 1e-4f                   // fwd/rev agreement margin

// ---------------- scratch ----------------
__device__ float  g_vndc[BMAX * VMAX * 3];
__device__ float4 g_rec[NFACE * 5];
__device__ float  g_zminf[NFACE];
__device__ int    g_fill[NTILEMAX];
__device__ int    g_listA[NTILEMAX * CAP];
__device__ int    g_listB[NTILEMAX * CAP];

__device__ __forceinline__ int zbucket(float z) {
    int q = (int)floorf((z - 0.5f) * 64.0f);
    return max(0, min(255, q));
}
__device__ __forceinline__ float zbound(int q) {
    return (q <= 0) ? 0.0f : (0.5f + (float)q * 0.015625f - 1e-4f);
}

// ---------------- projection ----------------
__global__ void project_kernel(const float* __restrict__ verts,
                               const float* __restrict__ K,
                               const float* __restrict__ R,
                               const float* __restrict__ t,
                               const float* __restrict__ dist,
                               int B, int V) {
    int idx = blockIdx.x * blockDim.x + threadIdx.x;
    if (idx >= B * V) return;
    int b = idx / V;
    const float* vp = verts + (size_t)idx * 3;
    const float* Rb = R + b * 9;
    const float* tb = t + b * 3;
    const float* Kb = K + b * 9;
    const float* db = dist + b * 5;

    float vx = vp[0], vy = vp[1], vz = vp[2];
    float x = Rb[0] * vx + Rb[1] * vy + Rb[2] * vz + tb[0];
    float y = Rb[3] * vx + Rb[4] * vy + Rb[5] * vz + tb[1];
    float z = Rb[6] * vx + Rb[7] * vy + Rb[8] * vz + tb[2];

    float x_ = x / (z + 1e-9f);
    float y_ = y / (z + 1e-9f);
    float k1 = db[0], k2 = db[1], p1 = db[2], p2 = db[3], k3 = db[4];
    float r2 = x_ * x_ + y_ * y_;
    float rad = 1.0f + k1 * r2 + k2 * r2 * r2 + k3 * r2 * r2 * r2;
    float x__ = x_ * rad + 2.0f * p1 * x_ * y_ + p2 * (r2 + 2.0f * x_ * x_);
    float y__ = y_ * rad + p1 * (r2 + 2.0f * y_ * y_) + 2.0f * p2 * x_ * y_;

    float u  = Kb[0] * x__ + Kb[1] * y__ + Kb[2];
    float vc = Kb[3] * x__ + Kb[4] * y__ + Kb[5];
    vc = ORIG - vc;
    u  = 2.0f * (u  - ORIG * 0.5f) / ORIG;
    vc = 2.0f * (vc - ORIG * 0.5f) / ORIG;

    float* o = g_vndc + (size_t)idx * 3;
    o[0] = u; o[1] = vc; o[2] = z;
}

// ---------------- merged prep + fill ----------------
__global__ void prepfill_kernel(const int* __restrict__ faces, int B, int V, int F) {
    int idx = blockIdx.x * blockDim.x + threadIdx.x;
    if (idx >= B * F) return;
    int b = idx / F;
    const int* fp = faces + (size_t)idx * 3;
    int i0 = fp[0], i1 = fp[1], i2 = fp[2];
    const float* base = g_vndc + (size_t)b * V * 3;
    float x0 = base[i0*3+0], y0 = base[i0*3+1], z0 = base[i0*3+2];
    float x1 = base[i1*3+0], y1 = base[i1*3+1], z1 = base[i1*3+2];
    float x2 = base[i2*3+0], y2 = base[i2*3+1], z2 = base[i2*3+2];

    if (!(z0 > REPS && z1 > REPS && z2 > REPS)) return;

    float df = (y1 - y2) * (x0 - x2) + (x2 - x1) * (y0 - y2);
    float dr = (y1 - y0) * (x2 - x0) + (x0 - x1) * (y2 - y0);
    bool okf = fabsf(df) > REPS;
    bool okr = fabsf(dr) > REPS;
    if (!okf && !okr) return;

    float xmin = fminf(x0, fminf(x1, x2)), xmax = fmaxf(x0, fmaxf(x1, x2));
    float ymin = fminf(y0, fminf(y1, y2)), ymax = fmaxf(y0, fmaxf(y1, y2));
    const float Sf = (float)IMG;
    int c_lo = max(0,       (int)floorf((xmin * Sf + Sf - 1.0f) * 0.5f));
    int c_hi = min(IMG - 1, (int)ceilf ((xmax * Sf + Sf - 1.0f) * 0.5f));
    int r_lo = max(0,       (int)floorf((ymin * Sf + Sf - 1.0f) * 0.5f));
    int r_hi = min(IMG - 1, (int)ceilf ((ymax * Sf + Sf - 1.0f) * 0.5f));
    if (c_lo > c_hi || r_lo > r_hi) return;

    float zmf = fminf(z0, fminf(z1, z2));
    g_zminf[idx] = zmf;

    float nanv = __int_as_float(0x7fffffff);
    float invdf = okf ? (1.0f / df) : nanv;
    float invdr = okr ? (1.0f / dr) : nanv;
    float iz0 = 1.0f / z0, iz1 = 1.0f / z1, iz2 = 1.0f / z2;

    float4 r0; r0.x = x2;      r0.y = y2;      r0.z = x0;      r0.w = y0;
    float4 r1; r1.x = y1 - y2; r1.y = x2 - x1; r1.z = y2 - y0; r1.w = x0 - x2;
    float4 r2f; r2f.x = y1 - y0; r2f.y = x0 - x1; r2f.z = y0 - y2; r2f.w = x2 - x0;
    float4 r3; r3.x = invdf;   r3.y = invdr;   r3.z = zmf;       r3.w = iz0 - iz2;  // af
    float4 r4; r4.x = iz1 - iz2; r4.y = iz2;   r4.z = iz1 - iz0; r4.w = iz0;        // bf,cf,br,cr
    g_rec[idx*5+0] = r0; g_rec[idx*5+1] = r1; g_rec[idx*5+2] = r2f;
    g_rec[idx*5+3] = r3; g_rec[idx*5+4] = r4;

    // fill: cheap corner-max edge cull, direct-indexed lists
    float a0 = r1.x * invdf, b0 = r1.y * invdf;
    float a1 = r1.z * invdf, b1 = r1.w * invdf;
    float a2 = -a0 - a1,     b2 = -b0 - b1;
    int tbase = b * TPI * TPI;
    int ty0 = r_lo >> 4, ty1 = r_hi >> 4;
    int tx0 = c_lo >> 4, tx1 = c_hi >> 4;

    for (int ty = ty0; ty <= ty1; ty++) {
        float ylo = (2.0f * (float)(ty * TSZ)           + 1.0f - Sf) / Sf - y2;
        float yhi = (2.0f * (float)(ty * TSZ + TSZ - 1) + 1.0f - Sf) / Sf - y2;
        for (int tx = tx0; tx <= tx1; tx++) {
            float xlo = (2.0f * (float)(tx * TSZ)           + 1.0f - Sf) / Sf - x2;
            float xhi = (2.0f * (float)(tx * TSZ + TSZ - 1) + 1.0f - Sf) / Sf - x2;

            float m0 = a0 * (a0 >= 0.f ? xhi : xlo) + b0 * (b0 >= 0.f ? yhi : ylo);
            float m1 = a1 * (a1 >= 0.f ? xhi : xlo) + b1 * (b1 >= 0.f ? yhi : ylo);
            float m2 = 1.0f + a2 * (a2 >= 0.f ? xhi : xlo) + b2 * (b2 >= 0.f ? yhi : ylo);
            if (m0 < -CULL_M || m1 < -CULL_M || m2 < -CULL_M) continue;

            int t = tbase + ty * TPI + tx;
            int pos = atomicAdd(&g_fill[t], 1);
            if (pos < CAP) g_listA[t * CAP + pos] = idx;
        }
    }
}

// ---------------- per-tile counting sort by z-bucket (shfl scan) ----------------
__global__ void sort_kernel() {
    int tile = blockIdx.x;
    int len  = min(g_fill[tile], CAP);
    if (len == 0) return;
    int base = tile * CAP;
    int tid = threadIdx.x;
    int lane = tid & 31, wrp = tid >> 5;
    const unsigned FULL = 0xffffffffu;

    __shared__ int cnt[256];
    __shared__ int off[256];
    __shared__ int wsum[8];
    cnt[tid] = 0;
    __syncthreads();

    for (int i = tid; i < len; i += 256) {
        int f = g_listA[base + i];
        atomicAdd(&cnt[zbucket(g_zminf[f])], 1);
    }
    __syncthreads();

    int v = cnt[tid];
    int x = v;
    #pragma unroll
    for (int o = 1; o < 32; o <<= 1) {
        int y = __shfl_up_sync(FULL, x, o);
        if (lane >= o) x += y;
    }
    if (lane == 31) wsum[wrp] = x;
    __syncthreads();
    if (tid < 8) {
        int s = wsum[tid];
        int xx = s;
        #pragma unroll
        for (int o = 1; o < 8; o <<= 1) {
            int y = __shfl_up_sync(0xffu, xx, o);
            if (tid >= o) xx += y;
        }
        wsum[tid] = xx - s;   // exclusive warp offset
    }
    __syncthreads();
    off[tid] = x + wsum[wrp] - v;   // exclusive prefix for bucket tid
    __syncthreads();

    for (int i = tid; i < len; i += 256) {
        int f = g_listA[base + i];
        int q = zbucket(g_zminf[f]);
        int pos = atomicAdd(&off[q], 1);
        g_listB[base + pos] = f;
    }
}

// ---------------- init output ----------------
__global__ void init_kernel(float* __restrict__ out, int n) {
    int i = blockIdx.x * blockDim.x + threadIdx.x;
    if (i < n) out[i] = FAR_F;
}

// ---------------- raster: slice split + early-z + margin-gated rev ----------------
__global__ void __launch_bounds__(256) raster_tiles(float* __restrict__ out) {
    int tile  = blockIdx.x / SPLITR;
    int slice = blockIdx.x % SPLITR;
    int len = min(g_fill[tile], CAP);
    if (len <= slice * CH) return;

    int b  = tile >> 8;
    int tt = tile & 255;
    int ty = tt >> 4, tx = tt & 15;
    int tid = threadIdx.x;
    int r = ty * TSZ + (tid >> 4);
    int c = tx * TSZ + (tid & 15);
    const float Sf = (float)IMG;
    float xp = (2.0f * (float)c + 1.0f - Sf) / Sf;
    float yp = (2.0f * (float)r + 1.0f - Sf) / Sf;

    int basei = tile * CAP;
    const unsigned FULL = 0xffffffffu;

    __shared__ float4 srec[CH * 5];
    float zmin = FAR_F;

    for (int j = slice * CH; j < len; j += CH * SPLITR) {
        int n = min(CH, len - j);
        __syncthreads();
        for (int k = tid; k < n * 5; k += 256) {
            int m = k / 5;
            int q = k - m * 5;
            int fidx = g_listB[basei + j + m];
            srec[k] = g_rec[fidx * 5 + q];
        }
        __syncthreads();

        float bound = zbound(zbucket(srec[3].z));
        if (__syncthreads_and(zmin <= bound)) break;

        for (int m = 0; m < n; m++) {
            float4 q3 = srec[m*5+3];
            if (!__ballot_sync(FULL, q3.z < zmin)) continue;

            float4 q0 = srec[m*5+0];
            float4 q1 = srec[m*5+1];

            float dxf = xp - q0.x, dyf = yp - q0.y;
            float w0 = (q1.x * dxf + q1.y * dyf) * q3.x;
            float w1 = (q1.z * dxf + q1.w * dyf) * q3.x;
            float w2 = 1.0f - w0 - w1;
            bool inf_ = (w0 >= 0.0f) && (w1 >= 0.0f) && (w2 >= 0.0f);
            // safe: far from every edge -> rev winding provably agrees
            bool safe = (fabsf(w0) > WMARG) && (fabsf(w1) > WMARG) && (fabsf(w2) > WMARG);

            bool in_ = inf_;
            bool userev = false;
            float w0r = 0.f, w1r = 0.f;
            if (__ballot_sync(FULL, !safe)) {
                float4 q2 = srec[m*5+2];
                float dxr = xp - q0.z, dyr = yp - q0.w;
                w0r = (q2.x * dxr + q2.y * dyr) * q3.y;
                w1r = (q2.z * dxr + q2.w * dyr) * q3.y;
                float w2r = 1.0f - w0r - w1r;
                bool inr_ = (w0r >= 0.0f) && (w1r >= 0.0f) && (w2r >= 0.0f);
                in_ = inf_ || inr_;
                userev = (!inf_) && inr_;
            }

            if (in_) {
                float4 q4 = srec[m*5+4];
                float zinv = userev ? fmaf(w1r, q4.z, fmaf(w0r, -q3.w, q4.w))
                                    : fmaf(w1,  q4.x, fmaf(w0,   q3.w, q4.y));
                float zp = (zinv > REPS) ? __fdividef(1.0f, zinv) : 1.0f;
                if (zp > NEAR_F && zp < FAR_F) zmin = fminf(zmin, zp);
            }
        }
    }

    if (zmin < FAR_F) {
        int* addr = (int*)&out[((size_t)b * IMG + (IMG - 1 - r)) * IMG + c];
        atomicMin(addr, __float_as_int(zmin));
    }
}

extern "C" void kernel_launch(void* const* d_in, const int* in_sizes, int n_in,
                              void* d_out, int out_size) {
    const float* verts = (const float*)d_in[0];
    const int*   faces = (const int*)d_in[1];
    const float* K     = (const float*)d_in[2];
    const float* R     = (const float*)d_in[3];
    const float* t     = (const float*)d_in[4];
    const float* dist  = (const float*)d_in[5];
    float* out = (float*)d_out;

    int B = in_sizes[2] / 9;
    int V = in_sizes[0] / (3 * B);
    int F = in_sizes[1] / (3 * B);
    int ntile = B * TPI * TPI;

    void* fill_ptr = nullptr;
    cudaGetSymbolAddress(&fill_ptr, g_fill);

    int nv = B * V;
    project_kernel<<<(nv + 255) / 256, 256>>>(verts, K, R, t, dist, B, V);

    cudaMemsetAsync(fill_ptr, 0, ntile * sizeof(int));

    int nf = B * F;
    prepfill_kernel<<<(nf + 255) / 256, 256>>>(faces, B, V, F);

    sort_kernel<<<ntile, 256>>>();

    int npix = B * IMG * IMG;
    init_kernel<<<(npix + 255) / 256, 256>>>(out, npix);

    raster_tiles<<<ntile * SPLITR, 256>>>(out);
}